// round 4
// baseline (speedup 1.0000x reference)
#include <cuda_runtime.h>

#define T     256
#define H     128
#define V     60
#define M     8            // batch rows per CTA
#define NT    256          // threads per CTA (8 warps, 2 per SMSP)
#define NCTA  128
#define CS    20           // swizzled h chunk stride (floats): kc*20 mod 32 all distinct
#define HR    160          // swizzled h row stride = 8 chunks * CS

typedef unsigned long long u64;

__device__ __align__(16) float g_proj[V * H];   // proj[v][j] = emb[v] . W_ih[j]

__device__ __forceinline__ void ffma2(u64& acc, u64 a, u64 b) {
    asm("fma.rn.f32x2 %0, %1, %2, %0;" : "+l"(acc) : "l"(a), "l"(b));
}
__device__ __forceinline__ float2 unpack2(u64 a) {
    float2 r;
    asm("mov.b64 {%0, %1}, %2;" : "=f"(r.x), "=f"(r.y) : "l"(a));
    return r;
}
__device__ __forceinline__ float fast_tanh(float x) {
    float e = __expf(2.0f * x);
    return 1.0f - __fdividef(2.0f, e + 1.0f);
}

// ---------------------------------------------------------------------------
// Stage 1: proj[v][j] = emb[v] . W_ih[j]   (60 x 128, trivial one-shot)
// ---------------------------------------------------------------------------
__global__ void proj_kernel(const float* __restrict__ emb,
                            const float* __restrict__ W_ih) {
    __shared__ float e[H];
    const int v = blockIdx.x;
    const int j = threadIdx.x;
    e[j] = emb[v * H + j];
    __syncthreads();
    const float* w = W_ih + j * H;
    float s = 0.f;
#pragma unroll 16
    for (int k = 0; k < H; ++k) s += e[k] * w[k];
    g_proj[v * H + j] = s;
}

// ---------------------------------------------------------------------------
// Stage 2: persistent recurrence. W_hh in REGISTERS (4j x 16k slice / thread),
// h via conflict-free swizzled SMEM, 8-way shuffle reduce-scatter per output.
// ---------------------------------------------------------------------------
__global__ __launch_bounds__(NT, 1)
void rnn_kernel(const int* __restrict__ x,
                const int* __restrict__ lengths,
                const float* __restrict__ W_hh,
                const float* __restrict__ W_fc,
                const float* __restrict__ b_fc,
                float* __restrict__ out) {
    extern __shared__ float smem[];
    float* Ps_ = smem;                       // V*H      proj table (linear)
    float* Hs_ = Ps_ + V * H;                // 2*M*HR   double-buffered hidden (swizzled)
    float* Ls_ = Hs_ + 2 * M * HR;           // M*H      hidden at t=len-1 (linear)
    int*   Tok = (int*)(Ls_ + M * H);        // M*T

    const int tid = threadIdx.x;
    const int b0  = blockIdx.x * M;

    // --- init smem ---
    for (int idx = tid; idx < V * (H / 4); idx += NT)
        ((float4*)Ps_)[idx] = ((const float4*)g_proj)[idx];
    for (int idx = tid; idx < M * T; idx += NT)
        Tok[idx] = x[b0 * T + idx];
    {
        float4 z4 = make_float4(0.f, 0.f, 0.f, 0.f);
        for (int idx = tid; idx < 2 * M * HR / 4; idx += NT)
            ((float4*)Hs_)[idx] = z4;
    }

    // --- decomposition: lane = jg(2b) | kc(3b). Thread owns j in [jb, jb+4),
    //     k in [kc*16, kc*16+16). 8 kc-threads (one octet) share each output. ---
    const int warp = tid >> 5, lane = tid & 31;
    const int jg = lane >> 3, kc = lane & 7;
    const int jb = warp * 16 + jg * 4;
    const int kb = kc * 16;

    // --- W_hh slice into registers: 32 floats = 16 u64 ---
    u64 Wr[4][8];
#pragma unroll
    for (int jj = 0; jj < 4; ++jj) {
        const ulonglong2* wp = (const ulonglong2*)(W_hh + (jb + jj) * H + kb);
#pragma unroll
        for (int q = 0; q < 4; ++q) {
            ulonglong2 v2 = wp[q];
            Wr[jj][2 * q]     = v2.x;
            Wr[jj][2 * q + 1] = v2.y;
        }
    }

    int lenm[M];
#pragma unroll
    for (int m = 0; m < M; ++m) lenm[m] = lengths[b0 + m];

    const int  jmy    = jb + (kc >> 1);                 // output j this lane finalizes
    const bool writer = ((kc & 1) == 0);
    const int  wsto   = (jmy >> 4) * CS + (jmy & 15);   // swizzled within-row offset
    const bool hi4    = (kc & 4) != 0;
    const bool hi2    = (kc & 2) != 0;

    __syncthreads();

    int cur = 0;
    for (int t = 0; t < T; ++t) {
        const float* Hc = Hs_ + cur * (M * HR);
        float*       Hn = Hs_ + (1 - cur) * (M * HR);

#pragma unroll
        for (int m = 0; m < M; ++m) {
            // h chunk: 16 floats, conflict-free (kc*CS mod 32 distinct), 16B-aligned
            const ulonglong2* hp = (const ulonglong2*)(Hc + m * HR + kc * CS);
            ulonglong2 ha = hp[0], hb2 = hp[1], hc2 = hp[2], hd2 = hp[3];
            u64 hv[8] = { ha.x, ha.y, hb2.x, hb2.y, hc2.x, hc2.y, hd2.x, hd2.y };

            u64 a0 = 0ull, a1 = 0ull, a2 = 0ull, a3 = 0ull;
#pragma unroll
            for (int p = 0; p < 8; ++p) {
                ffma2(a0, Wr[0][p], hv[p]);
                ffma2(a1, Wr[1][p], hv[p]);
                ffma2(a2, Wr[2][p], hv[p]);
                ffma2(a3, Wr[3][p], hv[p]);
            }
            float2 f0 = unpack2(a0), f1 = unpack2(a1), f2 = unpack2(a2), f3 = unpack2(a3);
            float p0 = f0.x + f0.y, p1 = f1.x + f1.y;
            float p2 = f2.x + f2.y, p3 = f3.x + f3.y;

            // 8-lane reduce-scatter (octet): lane kc ends with full sum for j = jb+(kc>>1)
            float o0 = __shfl_xor_sync(0xffffffffu, p0, 4, 8);
            float o1 = __shfl_xor_sync(0xffffffffu, p1, 4, 8);
            float o2 = __shfl_xor_sync(0xffffffffu, p2, 4, 8);
            float o3 = __shfl_xor_sync(0xffffffffu, p3, 4, 8);
            float q0 = hi4 ? (p2 + o2) : (p0 + o0);
            float q1 = hi4 ? (p3 + o3) : (p1 + o1);
            float r0 = __shfl_xor_sync(0xffffffffu, q0, 2, 8);
            float r1 = __shfl_xor_sync(0xffffffffu, q1, 2, 8);
            float s  = hi2 ? (q1 + r1) : (q0 + r0);
            float z  = s + __shfl_xor_sync(0xffffffffu, s, 1, 8);

            const int tk = Tok[m * T + t];
            z += Ps_[tk * H + jmy];
            float hval = fast_tanh(z);
            if (writer) {
                Hn[m * HR + wsto] = hval;
                if (t == lenm[m] - 1) Ls_[m * H + jmy] = hval;
            }
        }
        __syncthreads();
        cur ^= 1;
    }

    // --- FC epilogue: out[b] = last[b] @ W_fc^T + b_fc (reuse Ps_ for W_fc) ---
    for (int idx = tid; idx < V * (H / 4); idx += NT)
        ((float4*)Ps_)[idx] = ((const float4*)W_fc)[idx];
    __syncthreads();

    for (int p = tid; p < M * V; p += NT) {
        const int m = p / V, v = p % V;
        const float4* lr = (const float4*)(Ls_ + m * H);
        const float4* wr = (const float4*)(Ps_ + v * H);
        float s = b_fc[v];
#pragma unroll 8
        for (int q = 0; q < H / 4; ++q) {
            float4 l4 = lr[q], w4 = wr[q];
            s += l4.x * w4.x + l4.y * w4.y + l4.z * w4.z + l4.w * w4.w;
        }
        out[(b0 + m) * V + v] = s;
    }
}

extern "C" void kernel_launch(void* const* d_in, const int* in_sizes, int n_in,
                              void* d_out, int out_size) {
    const int*   x       = (const int*)d_in[0];
    const int*   lengths = (const int*)d_in[1];
    const float* emb     = (const float*)d_in[2];
    const float* W_ih    = (const float*)d_in[3];
    const float* W_hh    = (const float*)d_in[4];
    const float* W_fc    = (const float*)d_in[5];
    const float* b_fc    = (const float*)d_in[6];
    float*       out     = (float*)d_out;

    proj_kernel<<<V, H>>>(emb, W_ih);

    size_t smem = (size_t)(V * H + 2 * M * HR + M * H) * sizeof(float)
                + (size_t)(M * T) * sizeof(int);
    cudaFuncSetAttribute(rnn_kernel, cudaFuncAttributeMaxDynamicSharedMemorySize,
                         (int)smem);
    rnn_kernel<<<NCTA, NT, smem>>>(x, lengths, W_hh, W_fc, b_fc, out);
}

// round 6
// speedup vs baseline: 1.3316x; 1.3316x over previous
#include <cuda_runtime.h>

#define T     256
#define H     128
#define V     60
#define M     4            // batch rows per CTA
#define NT    256          // threads per CTA (8 warps)
#define NCTA  256          // 2 CTAs per SM target
#define CS    20           // swizzled h chunk stride (floats): kc*20 mod 32 all distinct
#define HR    160          // swizzled h row stride = 8 chunks * CS

typedef unsigned long long u64;

__device__ __align__(16) float g_proj[V * H];   // proj[v][j] = emb[v] . W_ih[j]

__device__ __forceinline__ void ffma2(u64& acc, u64 a, u64 b) {
    asm("fma.rn.f32x2 %0, %1, %2, %0;" : "+l"(acc) : "l"(a), "l"(b));
}
__device__ __forceinline__ float2 unpack2(u64 a) {
    float2 r;
    asm("mov.b64 {%0, %1}, %2;" : "=f"(r.x), "=f"(r.y) : "l"(a));
    return r;
}
__device__ __forceinline__ float fast_tanh(float x) {
    float e = __expf(2.0f * x);
    return 1.0f - __fdividef(2.0f, e + 1.0f);
}

// ---------------------------------------------------------------------------
// Stage 1: proj[v][j] = emb[v] . W_ih[j]   (60 x 128, trivial one-shot)
// ---------------------------------------------------------------------------
__global__ void proj_kernel(const float* __restrict__ emb,
                            const float* __restrict__ W_ih) {
    __shared__ float e[H];
    const int v = blockIdx.x;
    const int j = threadIdx.x;
    e[j] = emb[v * H + j];
    __syncthreads();
    const float* w = W_ih + j * H;
    float s = 0.f;
#pragma unroll 16
    for (int k = 0; k < H; ++k) s += e[k] * w[k];
    g_proj[v * H + j] = s;
}

// ---------------------------------------------------------------------------
// Stage 2: persistent recurrence. W_hh in registers (4j x 16k slice/thread),
// h via conflict-free swizzled SMEM, 8-way shuffle reduce-scatter per output.
// 2 CTAs per SM (M=4 rows each) for latency hiding.
// ---------------------------------------------------------------------------
__global__ __launch_bounds__(NT, 2)
void rnn_kernel(const int* __restrict__ x,
                const int* __restrict__ lengths,
                const float* __restrict__ W_hh,
                const float* __restrict__ W_fc,
                const float* __restrict__ b_fc,
                float* __restrict__ out) {
    extern __shared__ float smem[];
    float* Ps_ = smem;                       // V*H      proj table (linear)
    float* Hs_ = Ps_ + V * H;                // 2*M*HR   double-buffered hidden (swizzled)
    float* Ls_ = Hs_ + 2 * M * HR;           // M*H      hidden at t=len-1 (linear)
    int*   Tok = (int*)(Ls_ + M * H);        // M*T

    const int tid = threadIdx.x;
    const int b0  = blockIdx.x * M;

    // --- init smem ---
    for (int idx = tid; idx < V * (H / 4); idx += NT)
        ((float4*)Ps_)[idx] = ((const float4*)g_proj)[idx];
    for (int idx = tid; idx < M * T; idx += NT)
        Tok[idx] = x[b0 * T + idx];
    {
        float4 z4 = make_float4(0.f, 0.f, 0.f, 0.f);
        for (int idx = tid; idx < 2 * M * HR / 4; idx += NT)
            ((float4*)Hs_)[idx] = z4;
    }

    // --- decomposition: lane = jg(2b) | kc(3b). Thread owns j in [jb, jb+4),
    //     k in [kc*16, kc*16+16). 8 kc-threads (one octet) share each output. ---
    const int warp = tid >> 5, lane = tid & 31;
    const int jg = lane >> 3, kc = lane & 7;
    const int jb = warp * 16 + jg * 4;
    const int kb = kc * 16;

    // --- W_hh slice into registers: 32 floats = 16 u64 ---
    u64 Wr[4][8];
#pragma unroll
    for (int jj = 0; jj < 4; ++jj) {
        const ulonglong2* wp = (const ulonglong2*)(W_hh + (jb + jj) * H + kb);
#pragma unroll
        for (int q = 0; q < 4; ++q) {
            ulonglong2 v2 = wp[q];
            Wr[jj][2 * q]     = v2.x;
            Wr[jj][2 * q + 1] = v2.y;
        }
    }

    int lenm[M];
#pragma unroll
    for (int m = 0; m < M; ++m) lenm[m] = lengths[b0 + m];

    const int  jmy    = jb + (kc >> 1);                 // output j this lane finalizes
    const bool writer = ((kc & 1) == 0);
    const int  wsto   = (jmy >> 4) * CS + (jmy & 15);   // swizzled within-row offset
    const bool hi4    = (kc & 4) != 0;
    const bool hi2    = (kc & 2) != 0;

    __syncthreads();

    int cur = 0;
    for (int t = 0; t < T; ++t) {
        const float* Hc = Hs_ + cur * (M * HR);
        float*       Hn = Hs_ + (1 - cur) * (M * HR);

#pragma unroll
        for (int m = 0; m < M; ++m) {
            // h chunk: 16 floats, conflict-free (kc*CS mod 32 distinct), 16B-aligned
            const ulonglong2* hp = (const ulonglong2*)(Hc + m * HR + kc * CS);
            ulonglong2 ha = hp[0], hb2 = hp[1], hc2 = hp[2], hd2 = hp[3];
            u64 hv[8] = { ha.x, ha.y, hb2.x, hb2.y, hc2.x, hc2.y, hd2.x, hd2.y };

            u64 a0 = 0ull, a1 = 0ull, a2 = 0ull, a3 = 0ull;
#pragma unroll
            for (int p = 0; p < 8; ++p) {
                ffma2(a0, Wr[0][p], hv[p]);
                ffma2(a1, Wr[1][p], hv[p]);
                ffma2(a2, Wr[2][p], hv[p]);
                ffma2(a3, Wr[3][p], hv[p]);
            }
            float2 f0 = unpack2(a0), f1 = unpack2(a1), f2 = unpack2(a2), f3 = unpack2(a3);
            float p0 = f0.x + f0.y, p1 = f1.x + f1.y;
            float p2 = f2.x + f2.y, p3 = f3.x + f3.y;

            // 8-lane reduce-scatter (octet): lane kc ends with full sum for j = jb+(kc>>1)
            float o0 = __shfl_xor_sync(0xffffffffu, p0, 4, 8);
            float o1 = __shfl_xor_sync(0xffffffffu, p1, 4, 8);
            float o2 = __shfl_xor_sync(0xffffffffu, p2, 4, 8);
            float o3 = __shfl_xor_sync(0xffffffffu, p3, 4, 8);
            float q0 = hi4 ? (p2 + o2) : (p0 + o0);
            float q1 = hi4 ? (p3 + o3) : (p1 + o1);
            float r0 = __shfl_xor_sync(0xffffffffu, q0, 2, 8);
            float r1 = __shfl_xor_sync(0xffffffffu, q1, 2, 8);
            float s  = hi2 ? (q1 + r1) : (q0 + r0);
            float z  = s + __shfl_xor_sync(0xffffffffu, s, 1, 8);

            const int tk = Tok[m * T + t];
            z += Ps_[tk * H + jmy];
            float hval = fast_tanh(z);
            if (writer) {
                Hn[m * HR + wsto] = hval;
                if (t == lenm[m] - 1) Ls_[m * H + jmy] = hval;
            }
        }
        __syncthreads();
        cur ^= 1;
    }

    // --- FC epilogue: out[b] = last[b] @ W_fc^T + b_fc (reuse Ps_ for W_fc) ---
    for (int idx = tid; idx < V * (H / 4); idx += NT)
        ((float4*)Ps_)[idx] = ((const float4*)W_fc)[idx];
    __syncthreads();

    for (int p = tid; p < M * V; p += NT) {
        const int m = p / V, v = p % V;
        const float4* lr = (const float4*)(Ls_ + m * H);
        const float4* wr = (const float4*)(Ps_ + v * H);
        float s = b_fc[v];
#pragma unroll 8
        for (int q = 0; q < H / 4; ++q) {
            float4 l4 = lr[q], w4 = wr[q];
            s += l4.x * w4.x + l4.y * w4.y + l4.z * w4.z + l4.w * w4.w;
        }
        out[(b0 + m) * V + v] = s;
    }
}

extern "C" void kernel_launch(void* const* d_in, const int* in_sizes, int n_in,
                              void* d_out, int out_size) {
    const int*   x       = (const int*)d_in[0];
    const int*   lengths = (const int*)d_in[1];
    const float* emb     = (const float*)d_in[2];
    const float* W_ih    = (const float*)d_in[3];
    const float* W_hh    = (const float*)d_in[4];
    const float* W_fc    = (const float*)d_in[5];
    const float* b_fc    = (const float*)d_in[6];
    float*       out     = (float*)d_out;

    proj_kernel<<<V, H>>>(emb, W_ih);

    size_t smem = (size_t)(V * H + 2 * M * HR + M * H) * sizeof(float)
                + (size_t)(M * T) * sizeof(int);
    cudaFuncSetAttribute(rnn_kernel, cudaFuncAttributeMaxDynamicSharedMemorySize,
                         (int)smem);
    rnn_kernel<<<NCTA, NT, smem>>>(x, lengths, W_hh, W_fc, b_fc, out);
}

// round 8
// speedup vs baseline: 2.1153x; 1.5885x over previous
#include <cuda_runtime.h>
#include <cstdint>

#define T 256
#define H 128
#define V 60
#define M 8
#define NT 256
#define NCTA 128

typedef unsigned long long u64;

__device__ __align__(16) float g_proj[V * H];

__device__ __forceinline__ uint32_t to_tf32(float f) {
    uint32_t r;
    asm("cvt.rna.tf32.f32 %0, %1;" : "=r"(r) : "f"(f));
    return r;
}
__device__ __forceinline__ float fast_tanh(float x) {
    float e = __expf(2.0f * x);
    return 1.0f - __fdividef(2.0f, e + 1.0f);
}
__device__ __forceinline__ void mma_tf32(float& c0, float& c1, float& c2, float& c3,
                                         uint32_t a0, uint32_t a1, uint32_t a2, uint32_t a3,
                                         uint32_t b0, uint32_t b1) {
    asm volatile(
        "mma.sync.aligned.m16n8k8.row.col.f32.tf32.tf32.f32 "
        "{%0,%1,%2,%3}, {%4,%5,%6,%7}, {%8,%9}, {%0,%1,%2,%3};"
        : "+f"(c0), "+f"(c1), "+f"(c2), "+f"(c3)
        : "r"(a0), "r"(a1), "r"(a2), "r"(a3), "r"(b0), "r"(b1));
}

// h tile granule layout: float4 granule index = kt*32 + kk*8 + (m ^ kk),
// content = { hi(k), lo(k), hi(k+4), lo(k+4) },  k = kt*8 + kk.
__device__ __forceinline__ void store_h(float* Bn, int jn, int m, float h) {
    uint32_t hb = to_tf32(h);
    float hf = __uint_as_float(hb);
    uint32_t lb = to_tf32(h - hf);
    int kt = jn >> 3, kk = jn & 3;
    int g = kt * 32 + kk * 8 + (m ^ kk);
    int off = (jn & 4) ? 2 : 0;
    float2 v;
    v.x = __uint_as_float(hb);
    v.y = __uint_as_float(lb);
    *(float2*)(Bn + g * 4 + off) = v;
}

// ---------------------------------------------------------------------------
// Stage 1: proj[v][j] = emb[v] . W_ih[j]
// ---------------------------------------------------------------------------
__global__ void proj_kernel(const float* __restrict__ emb,
                            const float* __restrict__ W_ih) {
    __shared__ float e[H];
    const int v = blockIdx.x;
    const int j = threadIdx.x;
    e[j] = emb[v * H + j];
    __syncthreads();
    const float* w = W_ih + j * H;
    float s = 0.f;
#pragma unroll 16
    for (int k = 0; k < H; ++k) s += e[k] * w[k];
    g_proj[v * H + j] = s;
}

// ---------------------------------------------------------------------------
// Stage 2: persistent recurrence via 3xTF32 mma.sync (m16n8k8).
// Warp w owns output tile j in [16w, 16w+16), all 8 m. W fragments in regs.
// ---------------------------------------------------------------------------
__global__ __launch_bounds__(NT, 1)
void rnn_kernel(const int* __restrict__ x,
                const int* __restrict__ lengths,
                const float* __restrict__ W_hh,
                const float* __restrict__ W_fc,
                const float* __restrict__ b_fc,
                float* __restrict__ out) {
    extern __shared__ float sm[];
    float* B0 = sm;                    // 2048 floats: h tile buf 0 (512 granules)
    float* B1 = B0 + 2048;             // 2048 floats: h tile buf 1
    float* Ps = B1 + 2048;             // V*H proj (reused for W_fc)
    float* Ls = Ps + V * H;            // M*H last hidden
    int*   Tok = (int*)(Ls + M * H);   // M*T tokens

    const int tid = threadIdx.x;
    const int w = tid >> 5, l = tid & 31;
    const int b0 = blockIdx.x * M;

    // --- init smem ---
    for (int idx = tid; idx < V * (H / 4); idx += NT)
        ((float4*)Ps)[idx] = ((const float4*)g_proj)[idx];
    for (int idx = tid; idx < M * T; idx += NT)
        Tok[idx] = x[b0 * T + idx];

    // --- output-tile coordinates (mma C layout) ---
    const int jb = w * 16;
    const int j1 = jb + (l >> 2);        // rows of c0/c1
    const int j2 = j1 + 8;               // rows of c2/c3
    const int m1 = (l & 3) * 2;          // cols of c0/c2; c1/c3 = m1+1
    // B-fragment granule offset for this lane: kk = l&3, n = l>>2
    const int kkn = (l & 3) * 8 + ((l >> 2) ^ (l & 3));

    // --- W_hh fragments into registers (hi/lo tf32), mma A layout ---
    // a0=W[j1][kt*8+c], a1=W[j2][..], a2=W[j1][..+4], a3=W[j2][..+4], c=l&3
    uint32_t Ahi[16][4], Alo[16][4];
    {
        const int c = l & 3;
#pragma unroll
        for (int kt = 0; kt < 16; ++kt) {
            float w00 = W_hh[j1 * H + kt * 8 + c];
            float w10 = W_hh[j2 * H + kt * 8 + c];
            float w01 = W_hh[j1 * H + kt * 8 + 4 + c];
            float w11 = W_hh[j2 * H + kt * 8 + 4 + c];
            Ahi[kt][0] = to_tf32(w00);
            Ahi[kt][1] = to_tf32(w10);
            Ahi[kt][2] = to_tf32(w01);
            Ahi[kt][3] = to_tf32(w11);
            Alo[kt][0] = to_tf32(w00 - __uint_as_float(Ahi[kt][0]));
            Alo[kt][1] = to_tf32(w10 - __uint_as_float(Ahi[kt][1]));
            Alo[kt][2] = to_tf32(w01 - __uint_as_float(Ahi[kt][2]));
            Alo[kt][3] = to_tf32(w11 - __uint_as_float(Ahi[kt][3]));
        }
    }

    const int lenA = lengths[b0 + m1];
    const int lenB = lengths[b0 + m1 + 1];
    __syncthreads();

    // --- peel step 0: h1 = tanh(proj[x_0]) ---
    {
        int tkA = Tok[m1 * T], tkB = Tok[(m1 + 1) * T];
        float hA1 = fast_tanh(Ps[tkA * H + j1]);
        float hB1 = fast_tanh(Ps[tkB * H + j1]);
        float hA2 = fast_tanh(Ps[tkA * H + j2]);
        float hB2 = fast_tanh(Ps[tkB * H + j2]);
        if (lenA == 1) { Ls[m1 * H + j1] = hA1; Ls[m1 * H + j2] = hA2; }
        if (lenB == 1) { Ls[(m1 + 1) * H + j1] = hB1; Ls[(m1 + 1) * H + j2] = hB2; }
        store_h(B0, j1, m1, hA1);
        store_h(B0, j1, m1 + 1, hB1);
        store_h(B0, j2, m1, hA2);
        store_h(B0, j2, m1 + 1, hB2);
    }
    __syncthreads();

    for (int i = 1; i < T; ++i) {
        const float4* Bc = (const float4*)((i & 1) ? B0 : B1);
        float*        Bn = (i & 1) ? B1 : B0;

        float c0 = 0.f, c1 = 0.f, c2 = 0.f, c3 = 0.f;
#pragma unroll
        for (int kt = 0; kt < 16; ++kt) {
            float4 g = Bc[kt * 32 + kkn];
            uint32_t b0h = __float_as_uint(g.x), b0l = __float_as_uint(g.y);
            uint32_t b1h = __float_as_uint(g.z), b1l = __float_as_uint(g.w);
            mma_tf32(c0, c1, c2, c3, Ahi[kt][0], Ahi[kt][1], Ahi[kt][2], Ahi[kt][3], b0h, b1h);
            mma_tf32(c0, c1, c2, c3, Ahi[kt][0], Ahi[kt][1], Ahi[kt][2], Ahi[kt][3], b0l, b1l);
            mma_tf32(c0, c1, c2, c3, Alo[kt][0], Alo[kt][1], Alo[kt][2], Alo[kt][3], b0h, b1h);
        }

        // proj adds
        int tkA = Tok[m1 * T + i], tkB = Tok[(m1 + 1) * T + i];
        float zA1 = c0 + Ps[tkA * H + j1];
        float zB1 = c1 + Ps[tkB * H + j1];
        float zA2 = c2 + Ps[tkA * H + j2];
        float zB2 = c3 + Ps[tkB * H + j2];
        float hA1 = fast_tanh(zA1), hB1 = fast_tanh(zB1);
        float hA2 = fast_tanh(zA2), hB2 = fast_tanh(zB2);

        if (i == lenA - 1) { Ls[m1 * H + j1] = hA1; Ls[m1 * H + j2] = hA2; }
        if (i == lenB - 1) { Ls[(m1 + 1) * H + j1] = hB1; Ls[(m1 + 1) * H + j2] = hB2; }
        store_h(Bn, j1, m1, hA1);
        store_h(Bn, j1, m1 + 1, hB1);
        store_h(Bn, j2, m1, hA2);
        store_h(Bn, j2, m1 + 1, hB2);
        __syncthreads();
    }

    // --- FC epilogue: out[b] = Ls[b] @ W_fc^T + b_fc (reuse Ps for W_fc) ---
    for (int idx = tid; idx < V * (H / 4); idx += NT)
        ((float4*)Ps)[idx] = ((const float4*)W_fc)[idx];
    __syncthreads();

    for (int p = tid; p < M * V; p += NT) {
        const int m = p / V, v = p % V;
        const float4* lr = (const float4*)(Ls + m * H);
        const float4* wr = (const float4*)(Ps + v * H);
        float s = b_fc[v];
#pragma unroll 8
        for (int q = 0; q < H / 4; ++q) {
            float4 l4 = lr[q], w4 = wr[q];
            s += l4.x * w4.x + l4.y * w4.y + l4.z * w4.z + l4.w * w4.w;
        }
        out[(b0 + m) * V + v] = s;
    }
}

extern "C" void kernel_launch(void* const* d_in, const int* in_sizes, int n_in,
                              void* d_out, int out_size) {
    const int*   x       = (const int*)d_in[0];
    const int*   lengths = (const int*)d_in[1];
    const float* emb     = (const float*)d_in[2];
    const float* W_ih    = (const float*)d_in[3];
    const float* W_hh    = (const float*)d_in[4];
    const float* W_fc    = (const float*)d_in[5];
    const float* b_fc    = (const float*)d_in[6];
    float*       out     = (float*)d_out;

    proj_kernel<<<V, H>>>(emb, W_ih);

    size_t smem = (size_t)(2 * 2048 + V * H + M * H) * sizeof(float)
                + (size_t)(M * T) * sizeof(int);
    cudaFuncSetAttribute(rnn_kernel, cudaFuncAttributeMaxDynamicSharedMemorySize,
                         (int)smem);
    rnn_kernel<<<NCTA, NT, smem>>>(x, lengths, W_hh, W_fc, b_fc, out);
}

// round 10
// speedup vs baseline: 2.1773x; 1.0293x over previous
#include <cuda_runtime.h>
#include <cstdint>

#define T 256
#define H 128
#define V 60
#define M 8
#define NT 256
#define NCTA 128
#define PSW 132   // padded proj row stride: bank = (4*tk + j) % 32 -> conflict-free-ish

typedef unsigned long long u64;

__device__ __align__(16) float g_proj[V * H];

__device__ __forceinline__ uint32_t to_tf32(float f) {
    uint32_t r;
    asm("cvt.rna.tf32.f32 %0, %1;" : "=r"(r) : "f"(f));
    return r;
}
__device__ __forceinline__ float fast_tanh(float x) {
    float e = __expf(2.0f * x);
    return 1.0f - __fdividef(2.0f, e + 1.0f);
}
__device__ __forceinline__ void mma_tf32(float* c,
                                         uint32_t a0, uint32_t a1, uint32_t a2, uint32_t a3,
                                         uint32_t b0, uint32_t b1) {
    asm volatile(
        "mma.sync.aligned.m16n8k8.row.col.f32.tf32.tf32.f32 "
        "{%0,%1,%2,%3}, {%4,%5,%6,%7}, {%8,%9}, {%0,%1,%2,%3};"
        : "+f"(c[0]), "+f"(c[1]), "+f"(c[2]), "+f"(c[3])
        : "r"(a0), "r"(a1), "r"(a2), "r"(a3), "r"(b0), "r"(b1));
}

// h tile granule layout: float4 granule index = kt*32 + kk*8 + (m ^ kk),
// content = { hi(k), lo(k), hi(k+4), lo(k+4) },  k = kt*8 + kk.
__device__ __forceinline__ void store_h(float* Bn, int jn, int m, float h) {
    uint32_t hb = to_tf32(h);
    float hf = __uint_as_float(hb);
    uint32_t lb = to_tf32(h - hf);
    int kt = jn >> 3, kk = jn & 3;
    int g = kt * 32 + kk * 8 + (m ^ kk);
    int off = (jn & 4) ? 2 : 0;
    float2 v;
    v.x = __uint_as_float(hb);
    v.y = __uint_as_float(lb);
    *(float2*)(Bn + g * 4 + off) = v;
}

// ---------------------------------------------------------------------------
// Stage 1: proj[v][j] = emb[v] . W_ih[j]
// ---------------------------------------------------------------------------
__global__ void proj_kernel(const float* __restrict__ emb,
                            const float* __restrict__ W_ih) {
    __shared__ float e[H];
    const int v = blockIdx.x;
    const int j = threadIdx.x;
    e[j] = emb[v * H + j];
    __syncthreads();
    const float* w = W_ih + j * H;
    float s = 0.f;
#pragma unroll 16
    for (int k = 0; k < H; ++k) s += e[k] * w[k];
    g_proj[v * H + j] = s;
}

// ---------------------------------------------------------------------------
// Stage 2: persistent recurrence via 3xTF32 mma.sync (m16n8k8).
// Warp w owns output tile j in [16w, 16w+16), all 8 m. W fragments in regs.
// 6 independent accumulator chains (3 splits x kt parity) to break HMMA RAW.
// ---------------------------------------------------------------------------
__global__ __launch_bounds__(NT, 1)
void rnn_kernel(const int* __restrict__ x,
                const int* __restrict__ lengths,
                const float* __restrict__ W_hh,
                const float* __restrict__ W_fc,
                const float* __restrict__ b_fc,
                float* __restrict__ out) {
    extern __shared__ float sm[];
    float* B0 = sm;                    // 2048 floats: h tile buf 0 (512 granules)
    float* B1 = B0 + 2048;             // 2048 floats: h tile buf 1
    float* Ps = B1 + 2048;             // V*PSW proj (padded; reused for W_fc)
    float* Ls = Ps + V * PSW;          // M*H last hidden
    int*   Tok = (int*)(Ls + M * H);   // M*T tokens

    const int tid = threadIdx.x;
    const int w = tid >> 5, l = tid & 31;
    const int b0 = blockIdx.x * M;

    // --- init smem ---
    for (int idx = tid; idx < V * H; idx += NT) {
        int v = idx >> 7, j = idx & 127;
        Ps[v * PSW + j] = g_proj[idx];
    }
    for (int idx = tid; idx < M * T; idx += NT)
        Tok[idx] = x[b0 * T + idx];

    // --- output-tile coordinates (mma C layout) ---
    const int jb = w * 16;
    const int j1 = jb + (l >> 2);        // rows of c0/c1
    const int j2 = j1 + 8;               // rows of c2/c3
    const int m1 = (l & 3) * 2;          // cols of c0/c2; c1/c3 = m1+1
    // B-fragment granule offset for this lane: kk = l&3, n = l>>2
    const int kkn = (l & 3) * 8 + ((l >> 2) ^ (l & 3));

    // --- W_hh fragments into registers (hi/lo tf32), mma A layout ---
    uint32_t Ahi[16][4], Alo[16][4];
    {
        const int c = l & 3;
#pragma unroll
        for (int kt = 0; kt < 16; ++kt) {
            float w00 = W_hh[j1 * H + kt * 8 + c];
            float w10 = W_hh[j2 * H + kt * 8 + c];
            float w01 = W_hh[j1 * H + kt * 8 + 4 + c];
            float w11 = W_hh[j2 * H + kt * 8 + 4 + c];
            Ahi[kt][0] = to_tf32(w00);
            Ahi[kt][1] = to_tf32(w10);
            Ahi[kt][2] = to_tf32(w01);
            Ahi[kt][3] = to_tf32(w11);
            Alo[kt][0] = to_tf32(w00 - __uint_as_float(Ahi[kt][0]));
            Alo[kt][1] = to_tf32(w10 - __uint_as_float(Ahi[kt][1]));
            Alo[kt][2] = to_tf32(w01 - __uint_as_float(Ahi[kt][2]));
            Alo[kt][3] = to_tf32(w11 - __uint_as_float(Ahi[kt][3]));
        }
    }

    const int lenA = lengths[b0 + m1];
    const int lenB = lengths[b0 + m1 + 1];
    __syncthreads();

    // --- peel step 0: h1 = tanh(proj[x_0]) ---
    {
        int tkA = Tok[m1 * T], tkB = Tok[(m1 + 1) * T];
        float hA1 = fast_tanh(Ps[tkA * PSW + j1]);
        float hB1 = fast_tanh(Ps[tkB * PSW + j1]);
        float hA2 = fast_tanh(Ps[tkA * PSW + j2]);
        float hB2 = fast_tanh(Ps[tkB * PSW + j2]);
        if (lenA == 1) { Ls[m1 * H + j1] = hA1; Ls[m1 * H + j2] = hA2; }
        if (lenB == 1) { Ls[(m1 + 1) * H + j1] = hB1; Ls[(m1 + 1) * H + j2] = hB2; }
        store_h(B0, j1, m1, hA1);
        store_h(B0, j1, m1 + 1, hB1);
        store_h(B0, j2, m1, hA2);
        store_h(B0, j2, m1 + 1, hB2);
    }
    __syncthreads();

    for (int i = 1; i < T; ++i) {
        const float4* Bc = (const float4*)((i & 1) ? B0 : B1);
        float*        Bn = (i & 1) ? B1 : B0;

        // prefetch proj adds + tokens first: latency hides under MMA execution
        int tkA = Tok[m1 * T + i], tkB = Tok[(m1 + 1) * T + i];
        float pA1 = Ps[tkA * PSW + j1];
        float pB1 = Ps[tkB * PSW + j1];
        float pA2 = Ps[tkA * PSW + j2];
        float pB2 = Ps[tkB * PSW + j2];

        // 6 independent accumulator chains: [kt parity][split]
        float acc[2][3][4];
#pragma unroll
        for (int p = 0; p < 2; ++p)
#pragma unroll
            for (int s = 0; s < 3; ++s)
#pragma unroll
                for (int e = 0; e < 4; ++e) acc[p][s][e] = 0.f;

#pragma unroll
        for (int kt = 0; kt < 16; ++kt) {
            const int p = kt & 1;
            float4 g = Bc[kt * 32 + kkn];
            uint32_t b0h = __float_as_uint(g.x), b0l = __float_as_uint(g.y);
            uint32_t b1h = __float_as_uint(g.z), b1l = __float_as_uint(g.w);
            mma_tf32(acc[p][0], Ahi[kt][0], Ahi[kt][1], Ahi[kt][2], Ahi[kt][3], b0h, b1h);
            mma_tf32(acc[p][1], Ahi[kt][0], Ahi[kt][1], Ahi[kt][2], Ahi[kt][3], b0l, b1l);
            mma_tf32(acc[p][2], Alo[kt][0], Alo[kt][1], Alo[kt][2], Alo[kt][3], b0h, b1h);
        }

        float cc[4];
#pragma unroll
        for (int e = 0; e < 4; ++e)
            cc[e] = ((acc[0][0][e] + acc[1][0][e]) + (acc[0][1][e] + acc[1][1][e]))
                  + (acc[0][2][e] + acc[1][2][e]);

        float zA1 = cc[0] + pA1;
        float zB1 = cc[1] + pB1;
        float zA2 = cc[2] + pA2;
        float zB2 = cc[3] + pB2;
        float hA1 = fast_tanh(zA1), hB1 = fast_tanh(zB1);
        float hA2 = fast_tanh(zA2), hB2 = fast_tanh(zB2);

        if (i == lenA - 1) { Ls[m1 * H + j1] = hA1; Ls[m1 * H + j2] = hA2; }
        if (i == lenB - 1) { Ls[(m1 + 1) * H + j1] = hB1; Ls[(m1 + 1) * H + j2] = hB2; }
        store_h(Bn, j1, m1, hA1);
        store_h(Bn, j1, m1 + 1, hB1);
        store_h(Bn, j2, m1, hA2);
        store_h(Bn, j2, m1 + 1, hB2);
        __syncthreads();
    }

    // --- FC epilogue: out[b] = Ls[b] @ W_fc^T + b_fc (reuse Ps for W_fc) ---
    for (int idx = tid; idx < V * H; idx += NT) {
        int v = idx >> 7, j = idx & 127;
        Ps[v * PSW + j] = W_fc[idx];
    }
    __syncthreads();

    for (int p = tid; p < M * V; p += NT) {
        const int m = p / V, v = p % V;
        const float* lr = Ls + m * H;
        const float* wr = Ps + v * PSW;
        float s = b_fc[v];
#pragma unroll 8
        for (int k = 0; k < H; ++k) s += lr[k] * wr[k];
        out[(b0 + m) * V + v] = s;
    }
}

extern "C" void kernel_launch(void* const* d_in, const int* in_sizes, int n_in,
                              void* d_out, int out_size) {
    const int*   x       = (const int*)d_in[0];
    const int*   lengths = (const int*)d_in[1];
    const float* emb     = (const float*)d_in[2];
    const float* W_ih    = (const float*)d_in[3];
    const float* W_hh    = (const float*)d_in[4];
    const float* W_fc    = (const float*)d_in[5];
    const float* b_fc    = (const float*)d_in[6];
    float*       out     = (float*)d_out;

    proj_kernel<<<V, H>>>(emb, W_ih);

    size_t smem = (size_t)(2 * 2048 + V * PSW + M * H) * sizeof(float)
                + (size_t)(M * T) * sizeof(int);
    cudaFuncSetAttribute(rnn_kernel, cudaFuncAttributeMaxDynamicSharedMemorySize,
                         (int)smem);
    rnn_kernel<<<NCTA, NT, smem>>>(x, lengths, W_hh, W_fc, b_fc, out);
}

// round 11
// speedup vs baseline: 3.2260x; 1.4816x over previous
#include <cuda_runtime.h>
#include <cuda_fp16.h>
#include <cstdint>

#define T 256
#define H 128
#define V 60
#define M 8
#define NT 256
#define NCTA 128
#define PSW 132   // padded proj row stride

typedef unsigned long long u64;

__device__ __align__(16) float g_proj[V * H];

__device__ __forceinline__ float fast_tanh(float x) {
    float e = __expf(2.0f * x);
    return 1.0f - __fdividef(2.0f, e + 1.0f);
}
__device__ __forceinline__ void mma_f16(float* c, const uint32_t* a,
                                        uint32_t b0, uint32_t b1) {
    asm volatile(
        "mma.sync.aligned.m16n8k16.row.col.f32.f16.f16.f32 "
        "{%0,%1,%2,%3}, {%4,%5,%6,%7}, {%8,%9}, {%0,%1,%2,%3};"
        : "+f"(c[0]), "+f"(c[1]), "+f"(c[2]), "+f"(c[3])
        : "r"(a[0]), "r"(a[1]), "r"(a[2]), "r"(a[3]), "r"(b0), "r"(b1));
}
// split a float pair into packed fp16 hi and lo words (low half = first elem)
__device__ __forceinline__ uint32_t split_pack(float2 v, uint32_t& lo) {
    __half h0 = __float2half_rn(v.x), h1 = __float2half_rn(v.y);
    __half l0 = __float2half_rn(v.x - __half2float(h0));
    __half l1 = __float2half_rn(v.y - __half2float(h1));
    lo = ((uint32_t)__half_as_ushort(l1) << 16) | __half_as_ushort(l0);
    return ((uint32_t)__half_as_ushort(h1) << 16) | __half_as_ushort(h0);
}
__device__ __forceinline__ void split1(float h, unsigned short& hi, unsigned short& lo) {
    __half hh = __float2half_rn(h);
    __half ll = __float2half_rn(h - __half2float(hh));
    hi = __half_as_ushort(hh);
    lo = __half_as_ushort(ll);
}

// h tile: per warp-ktile w, granule float4 idx G = w*32 + kq*8 + (n ^ kq),
// content words = { hi(2kq,2kq+1), lo(2kq,2kq+1), hi(+8), lo(+8) } fp16x2, n = batch m.
// Thread (g = l>>2, c = l&3) owns j1 = 16w+g (k elem parity g&1 of pair kq=g>>1),
// j2 = j1+8, for m = 2c, 2c+1 -> eight 16-bit stores.
__device__ __forceinline__ void store_h4(float* Bn, int w, int g, int mA, int mB,
                                         float hA1, float hB1, float hA2, float hB2) {
    const int kq = g >> 1, par = g & 1;
    char* bb = (char*)Bn;
    const int GA = (w * 32 + kq * 8 + (mA ^ kq)) * 16 + par * 2;
    const int GB = (w * 32 + kq * 8 + (mB ^ kq)) * 16 + par * 2;
    unsigned short x, y;
    split1(hA1, x, y);
    *(unsigned short*)(bb + GA + 0) = x;
    *(unsigned short*)(bb + GA + 4) = y;
    split1(hA2, x, y);
    *(unsigned short*)(bb + GA + 8)  = x;
    *(unsigned short*)(bb + GA + 12) = y;
    split1(hB1, x, y);
    *(unsigned short*)(bb + GB + 0) = x;
    *(unsigned short*)(bb + GB + 4) = y;
    split1(hB2, x, y);
    *(unsigned short*)(bb + GB + 8)  = x;
    *(unsigned short*)(bb + GB + 12) = y;
}

// ---------------------------------------------------------------------------
// Stage 1: proj[v][j] = emb[v] . W_ih[j]
// ---------------------------------------------------------------------------
__global__ void proj_kernel(const float* __restrict__ emb,
                            const float* __restrict__ W_ih) {
    __shared__ float e[H];
    const int v = blockIdx.x;
    const int j = threadIdx.x;
    e[j] = emb[v * H + j];
    __syncthreads();
    const float* w = W_ih + j * H;
    float s = 0.f;
#pragma unroll 16
    for (int k = 0; k < H; ++k) s += e[k] * w[k];
    g_proj[v * H + j] = s;
}

// ---------------------------------------------------------------------------
// Stage 2: persistent recurrence via 3-term fp16-split mma.sync (m16n8k16).
// Warp w owns output j in [16w, 16w+16), all 8 m. W fragments in registers.
// ---------------------------------------------------------------------------
__global__ __launch_bounds__(NT, 1)
void rnn_kernel(const int* __restrict__ x,
                const int* __restrict__ lengths,
                const float* __restrict__ W_hh,
                const float* __restrict__ W_fc,
                const float* __restrict__ b_fc,
                float* __restrict__ out) {
    extern __shared__ float sm[];
    float* B0 = sm;                    // 1024 floats: h tile buf 0 (256 granules)
    float* B1 = B0 + 1024;             // 1024 floats: h tile buf 1
    float* Ps = B1 + 1024;             // V*PSW proj (padded; reused for W_fc)
    float* Ls = Ps + V * PSW;          // M*H last hidden
    int*   Tok = (int*)(Ls + M * H);   // M*T tokens

    const int tid = threadIdx.x;
    const int w = tid >> 5, l = tid & 31;
    const int b0 = blockIdx.x * M;

    // --- init smem ---
    for (int idx = tid; idx < V * H; idx += NT) {
        int v = idx >> 7, j = idx & 127;
        Ps[v * PSW + j] = g_proj[idx];
    }
    for (int idx = tid; idx < M * T; idx += NT)
        Tok[idx] = x[b0 * T + idx];

    // --- coordinates ---
    const int g = l >> 2, c = l & 3;
    const int j1 = w * 16 + g;           // rows of c0/c1
    const int j2 = j1 + 8;               // rows of c2/c3
    const int m1 = c * 2;                // cols of c0/c2; c1/c3 = m1+1
    const int kkn = c * 8 + (g ^ c);     // B granule offset (load side)

    // --- W_hh fragments (fp16 hi/lo), m16n8k16 A layout ---
    // a0=(j1, k=2c,2c+1), a1=(j2, same), a2=(j1, k+8 pair), a3=(j2, k+8 pair)
    uint32_t Ahi[8][4], Alo[8][4];
#pragma unroll
    for (int kt = 0; kt < 8; ++kt) {
        float2 wa = *(const float2*)&W_hh[j1 * H + kt * 16 + 2 * c];
        float2 wb = *(const float2*)&W_hh[j2 * H + kt * 16 + 2 * c];
        float2 wc = *(const float2*)&W_hh[j1 * H + kt * 16 + 8 + 2 * c];
        float2 wd = *(const float2*)&W_hh[j2 * H + kt * 16 + 8 + 2 * c];
        Ahi[kt][0] = split_pack(wa, Alo[kt][0]);
        Ahi[kt][1] = split_pack(wb, Alo[kt][1]);
        Ahi[kt][2] = split_pack(wc, Alo[kt][2]);
        Ahi[kt][3] = split_pack(wd, Alo[kt][3]);
    }

    const int lenA = lengths[b0 + m1];
    const int lenB = lengths[b0 + m1 + 1];
    __syncthreads();

    // --- peel step 0: h1 = tanh(proj[x_0]) ---
    {
        int tkA = Tok[m1 * T], tkB = Tok[(m1 + 1) * T];
        float hA1 = fast_tanh(Ps[tkA * PSW + j1]);
        float hB1 = fast_tanh(Ps[tkB * PSW + j1]);
        float hA2 = fast_tanh(Ps[tkA * PSW + j2]);
        float hB2 = fast_tanh(Ps[tkB * PSW + j2]);
        if (lenA == 1) { Ls[m1 * H + j1] = hA1; Ls[m1 * H + j2] = hA2; }
        if (lenB == 1) { Ls[(m1 + 1) * H + j1] = hB1; Ls[(m1 + 1) * H + j2] = hB2; }
        store_h4(B0, w, g, m1, m1 + 1, hA1, hB1, hA2, hB2);
    }
    __syncthreads();

    for (int i = 1; i < T; ++i) {
        const float4* Bc = (const float4*)((i & 1) ? B0 : B1);
        float*        Bn = (i & 1) ? B1 : B0;

        // prefetch proj adds + tokens (hide under MMA)
        int tkA = Tok[m1 * T + i], tkB = Tok[(m1 + 1) * T + i];
        float pA1 = Ps[tkA * PSW + j1];
        float pB1 = Ps[tkB * PSW + j1];
        float pA2 = Ps[tkA * PSW + j2];
        float pB2 = Ps[tkB * PSW + j2];

        // 6 independent accumulator chains: [kt parity][split term]
        float acc[2][3][4];
#pragma unroll
        for (int p = 0; p < 2; ++p)
#pragma unroll
            for (int s = 0; s < 3; ++s)
#pragma unroll
                for (int e = 0; e < 4; ++e) acc[p][s][e] = 0.f;

#pragma unroll
        for (int kt = 0; kt < 8; ++kt) {
            const int p = kt & 1;
            float4 gr = Bc[kt * 32 + kkn];
            uint32_t bh0 = __float_as_uint(gr.x), bl0 = __float_as_uint(gr.y);
            uint32_t bh1 = __float_as_uint(gr.z), bl1 = __float_as_uint(gr.w);
            mma_f16(acc[p][0], Ahi[kt], bh0, bh1);
            mma_f16(acc[p][1], Ahi[kt], bl0, bl1);
            mma_f16(acc[p][2], Alo[kt], bh0, bh1);
        }

        float cc[4];
#pragma unroll
        for (int e = 0; e < 4; ++e)
            cc[e] = ((acc[0][0][e] + acc[1][0][e]) + (acc[0][1][e] + acc[1][1][e]))
                  + (acc[0][2][e] + acc[1][2][e]);

        float hA1 = fast_tanh(cc[0] + pA1);
        float hB1 = fast_tanh(cc[1] + pB1);
        float hA2 = fast_tanh(cc[2] + pA2);
        float hB2 = fast_tanh(cc[3] + pB2);

        if (i == lenA - 1) { Ls[m1 * H + j1] = hA1; Ls[m1 * H + j2] = hA2; }
        if (i == lenB - 1) { Ls[(m1 + 1) * H + j1] = hB1; Ls[(m1 + 1) * H + j2] = hB2; }
        store_h4(Bn, w, g, m1, m1 + 1, hA1, hB1, hA2, hB2);
        __syncthreads();
    }

    // --- FC epilogue: out[b] = Ls[b] @ W_fc^T + b_fc (reuse Ps for W_fc) ---
    for (int idx = tid; idx < V * H; idx += NT) {
        int v = idx >> 7, j = idx & 127;
        Ps[v * PSW + j] = W_fc[idx];
    }
    __syncthreads();

    for (int p = tid; p < M * V; p += NT) {
        const int m = p / V, v = p % V;
        const float* lr = Ls + m * H;
        const float* wr = Ps + v * PSW;
        float s = b_fc[v];
#pragma unroll 8
        for (int k = 0; k < H; ++k) s += lr[k] * wr[k];
        out[(b0 + m) * V + v] = s;
    }
}

extern "C" void kernel_launch(void* const* d_in, const int* in_sizes, int n_in,
                              void* d_out, int out_size) {
    const int*   x       = (const int*)d_in[0];
    const int*   lengths = (const int*)d_in[1];
    const float* emb     = (const float*)d_in[2];
    const float* W_ih    = (const float*)d_in[3];
    const float* W_hh    = (const float*)d_in[4];
    const float* W_fc    = (const float*)d_in[5];
    const float* b_fc    = (const float*)d_in[6];
    float*       out     = (float*)d_out;

    proj_kernel<<<V, H>>>(emb, W_ih);

    size_t smem = (size_t)(2 * 1024 + V * PSW + M * H) * sizeof(float)
                + (size_t)(M * T) * sizeof(int);
    cudaFuncSetAttribute(rnn_kernel, cudaFuncAttributeMaxDynamicSharedMemorySize,
                         (int)smem);
    rnn_kernel<<<NCTA, NT, smem>>>(x, lengths, W_hh, W_fc, b_fc, out);
}